// round 11
// baseline (speedup 1.0000x reference)
#include <cuda_runtime.h>
#include <cuda_fp16.h>
#include <stdint.h>

#define DDIM   2048
#define TILE_M 128
#define TILE_N 256
#define TILE_K 32
#define NKS    (DDIM / TILE_K)      // 64 k-stages
#define STAGES 8
#define NMAX   16384
#define CMAX   8192

#define A_BLK  (TILE_M * TILE_K * 2)   // 8192 bytes per (m-tile, k-stage)
#define B_BLK  (TILE_N * TILE_K * 2)   // 16384 bytes
#define SLOT   (A_BLK + B_BLK)         // 24576
#define SMEM_BYTES (1024 + STAGES * SLOT)   // 197632

// Packed, pre-swizzled fp16 operands (allocation-free scratch)
__device__ __align__(1024) char g_fn[(size_t)NMAX * DDIM * 2];   // 64 MB
__device__ __align__(1024) char g_pn[(size_t)CMAX * DDIM * 2];   // 32 MB

// ------------------------------ PTX helpers -----------------------------
__device__ __forceinline__ uint32_t smem_u32(const void* p) {
  uint32_t a;
  asm("{ .reg .u64 t; cvta.to.shared.u64 t, %1; cvt.u32.u64 %0, t; }" : "=r"(a) : "l"(p));
  return a;
}

#define MBAR_INIT(a, c) asm volatile("mbarrier.init.shared.b64 [%0], %1;" :: "r"(a), "r"(c) : "memory")
#define MBAR_ARRIVE(a)  asm volatile("mbarrier.arrive.shared.b64 _, [%0];" :: "r"(a) : "memory")
#define MBAR_EXPECT_TX(a, n) \
  asm volatile("mbarrier.arrive.expect_tx.shared.b64 _, [%0], %1;" :: "r"(a), "r"(n) : "memory")

#define MBAR_WAIT(a, par) do {                                                              \
  uint32_t _m = (a); uint32_t _p = (par); uint32_t _ok;                                     \
  asm volatile("{\n\t.reg .pred p;\n\t"                                                     \
    "mbarrier.try_wait.parity.acquire.cta.shared::cta.b64 p, [%1], %2;\n\t"                 \
    "selp.b32 %0, 1, 0, p;\n\t}" : "=r"(_ok) : "r"(_m), "r"(_p) : "memory");                \
  if (!_ok) {                                                                               \
    asm volatile("{\n\t.reg .pred P1;\n\t"                                                  \
      "WL_%=:\n\t"                                                                          \
      "mbarrier.try_wait.parity.acquire.cta.shared::cta.b64 P1, [%0], %1, 0x989680;\n\t"    \
      "@P1 bra.uni WD_%=;\n\t"                                                              \
      "bra.uni WL_%=;\n\t"                                                                  \
      "WD_%=:\n\t}" :: "r"(_m), "r"(_p) : "memory");                                        \
  }                                                                                         \
} while (0)

// non-tensor bulk copy gmem -> smem with transaction-count completion (sm_90, non-a)
__device__ __forceinline__ void bulk_g2s(uint32_t dst, const void* src, uint32_t bytes,
                                         uint32_t mbar) {
  asm volatile(
    "cp.async.bulk.shared::cluster.global.mbarrier::complete_tx::bytes [%0], [%1], %2, [%3];"
    :: "r"(dst), "l"(src), "r"(bytes), "r"(mbar) : "memory");
}

__device__ __forceinline__ void ldmx4(uint32_t* r, uint32_t addr) {
  asm volatile("ldmatrix.sync.aligned.m8n8.x4.shared.b16 {%0,%1,%2,%3}, [%4];"
               : "=r"(r[0]), "=r"(r[1]), "=r"(r[2]), "=r"(r[3]) : "r"(addr));
}

// fp16 MMA with fp16 accumulator (2 dest regs — probing RF-write-limited rt)
__device__ __forceinline__ void mma16816h(uint32_t* d, const uint32_t* a,
                                          uint32_t b0, uint32_t b1) {
  asm volatile(
    "mma.sync.aligned.m16n8k16.row.col.f16.f16.f16.f16 "
    "{%0,%1}, {%2,%3,%4,%5}, {%6,%7}, {%0,%1};"
    : "+r"(d[0]), "+r"(d[1])
    : "r"(a[0]), "r"(a[1]), "r"(a[2]), "r"(a[3]), "r"(b0), "r"(b1));
}

__device__ __forceinline__ uint32_t h2_as_u32(__half2 v) {
  return *reinterpret_cast<uint32_t*>(&v);
}

// --------------------------- normalize + pack (fp16) --------------------
// Output layout: per (row-tile mt, 32-elem k-slice kt) a contiguous block of
// tile_rows*64 bytes; row rm holds its slice as 4 16B chunks, chunk c stored
// at c ^ ((rm>>1)&3) (conflict-free for ldmatrix).
__device__ __forceinline__ void pack4(char* rowbase, int t2, float x, float y, float z,
                                      float w, float sc, size_t bstride, uint32_t s) {
  const int kt = t2 >> 3;
  const uint32_t cp = ((uint32_t)t2 & 7) >> 1;
  const uint32_t byo = ((uint32_t)t2 & 1) * 8;
  uint2 v;
  v.x = h2_as_u32(__float22half2_rn(make_float2(x * sc, y * sc)));
  v.y = h2_as_u32(__float22half2_rn(make_float2(z * sc, w * sc)));
  *reinterpret_cast<uint2*>(rowbase + (size_t)kt * bstride + ((cp ^ s) << 4) + byo) = v;
}

__global__ void norm_pack_kernel(const float* __restrict__ src, char* __restrict__ dst,
                                 int tile_rows) {
  const int row = blockIdx.x;
  const int tid = threadIdx.x;
  const float4* s4 = reinterpret_cast<const float4*>(src + (size_t)row * DDIM);
  float4 v0 = s4[tid];
  float4 v1 = s4[tid + 256];
  float acc = v0.x * v0.x + v0.y * v0.y + v0.z * v0.z + v0.w * v0.w
            + v1.x * v1.x + v1.y * v1.y + v1.z * v1.z + v1.w * v1.w;
#pragma unroll
  for (int o = 16; o > 0; o >>= 1) acc += __shfl_xor_sync(0xFFFFFFFFu, acc, o);
  __shared__ float red[8];
  if ((tid & 31) == 0) red[tid >> 5] = acc;
  __syncthreads();
  float tot = 0.f;
#pragma unroll
  for (int i = 0; i < 8; i++) tot += red[i];
  const float sc = 1.0f / fmaxf(sqrtf(tot), 1e-12f);

  const int mt = row / tile_rows;
  const int rm = row % tile_rows;
  const size_t bstride = (size_t)tile_rows * 64;
  char* rowbase = dst + (size_t)mt * 64 * bstride + (size_t)rm * 64;
  const uint32_t s = ((uint32_t)rm >> 1) & 3;
  pack4(rowbase, tid, v0.x, v0.y, v0.z, v0.w, sc, bstride, s);
  pack4(rowbase, tid + 256, v1.x, v1.y, v1.z, v1.w, sc, bstride, s);
}

// --------------------------- GEMM + distance ----------------------------
// CTA tile 128x256, 8 warps 2(M)x4(N), warp tile 64x64, mma m16n8k16 f16acc.
// Stage-PAIR loop: per (i,j) tile a K=64 fp16 chunk (4 chained MMAs) is
// promoted into the fp32 master accumulator (two-level accumulation).
__global__ __launch_bounds__(256, 1)
void gemm_dist_kernel(const char* __restrict__ Apk, const char* __restrict__ Bpk,
                      const float* __restrict__ dscale,
                      float* __restrict__ out, int Crows) {
  extern __shared__ __align__(1024) char smem[];
  const uint32_t sb = smem_u32(smem);
  const int tid = threadIdx.x;
  const int wid = tid >> 5;
  const int lane = tid & 31;

  // supertile mapping: groups of 4 m-tiles x all n-tiles keep B L2-resident
  const int nt = Crows / TILE_N;                 // 32
  const int per_sg = 4 * nt;                     // 128
  const int sg = blockIdx.x / per_sg;
  const int r = blockIdx.x % per_sg;
  const int m_tile = sg * 4 + (r & 3);
  const int n_tile = r >> 2;

  const char* Abase = Apk + (size_t)m_tile * NKS * A_BLK;
  const char* Bbase = Bpk + (size_t)n_tile * NKS * B_BLK;

  // barriers: full[s] @ sb + s*8 ; empty[s] @ sb + 128 + s*8
  if (tid == 0) {
#pragma unroll
    for (int s = 0; s < STAGES; s++) {
      MBAR_INIT(sb + s * 8, 1);
      MBAR_INIT(sb + 128 + s * 8, 8);
    }
  }
  __syncthreads();

  auto produce = [&](int t) {
    const int ts = t & (STAGES - 1);
    MBAR_WAIT(sb + 128 + ts * 8, ((t / STAGES) - 1) & 1);       // slot free
    const uint32_t full = sb + ts * 8;
    const uint32_t pslot = sb + 1024 + ts * SLOT;
    MBAR_EXPECT_TX(full, SLOT);
    bulk_g2s(pslot, Abase + (size_t)t * A_BLK, A_BLK, full);
    bulk_g2s(pslot + A_BLK, Bbase + (size_t)t * B_BLK, B_BLK, full);
  };

  if (tid == 0) {
#pragma unroll
    for (int t = 0; t < STAGES - 1; t++) produce(t);
  }

  // per-lane ldmatrix addressing constants
  const int wm = wid & 1;
  const int wn = wid >> 1;
  const uint32_t sA = (((uint32_t)lane & 15) >> 1) & 3;
  const uint32_t sB = (((uint32_t)lane & 7) >> 1) & 3;
  const uint32_t aRowOff = (uint32_t)(wm * 64 + (lane & 15)) * 64;
  const uint32_t aChunkHalf = (uint32_t)(lane >> 4);
  const uint32_t bRowOff = (uint32_t)(wn * 64 + (lane >> 4) * 8 + (lane & 7)) * 64;
  const uint32_t bChunkHalf = ((uint32_t)lane >> 3) & 1;

  float acc[4][8][4];
#pragma unroll
  for (int i = 0; i < 4; i++)
#pragma unroll
    for (int j = 0; j < 8; j++)
#pragma unroll
      for (int c = 0; c < 4; c++) acc[i][j][c] = 0.f;

  for (int p = 0; p < NKS / 2; p++) {
    const int s0 = 2 * p;

    // produce stage s0+7 (slot of stage s0-1, fully consumed in pair p-1)
    if (tid == 0 && s0 + STAGES - 1 < NKS) produce(s0 + STAGES - 1);

    const int is0 = s0 & (STAGES - 1);            // even, so is1 = is0+1
    MBAR_WAIT(sb + is0 * 8, (s0 / STAGES) & 1);
    MBAR_WAIT(sb + (is0 + 1) * 8, ((s0 + 1) / STAGES) & 1);
    const uint32_t slot0 = sb + 1024 + (uint32_t)is0 * SLOT;
    const uint32_t slot1 = slot0 + SLOT;

    // front-batch all B fragments for both stages of the pair
    uint32_t bfr[2][2][4][4];
#pragma unroll
    for (int st = 0; st < 2; st++) {
      const uint32_t sl = st ? slot1 : slot0;
#pragma unroll
      for (int ks = 0; ks < 2; ks++) {
        const uint32_t cb = (((uint32_t)ks * 2 + bChunkHalf) ^ sB) << 4;
#pragma unroll
        for (int jp = 0; jp < 4; jp++)
          ldmx4(bfr[st][ks][jp], sl + A_BLK + bRowOff + jp * 1024 + cb);
      }
    }

#pragma unroll
    for (int i = 0; i < 4; i++) {
      uint32_t afr[2][2][4];
#pragma unroll
      for (int st = 0; st < 2; st++) {
        const uint32_t sl = st ? slot1 : slot0;
#pragma unroll
        for (int ks = 0; ks < 2; ks++) {
          const uint32_t ca = (((uint32_t)ks * 2 + aChunkHalf) ^ sA) << 4;
          ldmx4(afr[st][ks], sl + aRowOff + i * 1024 + ca);
        }
      }
#pragma unroll
      for (int j = 0; j < 8; j++) {
        uint32_t t16[2] = {0u, 0u};               // fp16 K=64 chunk accumulator
#pragma unroll
        for (int st = 0; st < 2; st++)
#pragma unroll
          for (int ks = 0; ks < 2; ks++)
            mma16816h(t16, afr[st][ks],
                      bfr[st][ks][j >> 1][(j & 1) * 2],
                      bfr[st][ks][j >> 1][(j & 1) * 2 + 1]);
        const float2 lo = __half22float2(*reinterpret_cast<const __half2*>(&t16[0]));
        const float2 hi = __half22float2(*reinterpret_cast<const __half2*>(&t16[1]));
        acc[i][j][0] += lo.x; acc[i][j][1] += lo.y;
        acc[i][j][2] += hi.x; acc[i][j][3] += hi.y;
      }
    }

    if (lane == 0) {
      MBAR_ARRIVE(sb + 128 + is0 * 8);
      MBAR_ARRIVE(sb + 128 + (is0 + 1) * 8);
    }
    // produce stage s0+8 AFTER this pair consumed s0 (deadlock-free order)
    if (tid == 0 && s0 + STAGES < NKS) produce(s0 + STAGES);
  }

  // fused distance epilogue
  const float sc = fabsf(dscale[0]);
  const int g = lane >> 2;
  const int tq = lane & 3;
  const int m0 = m_tile * TILE_M + wm * 64 + g;
  const int n0 = n_tile * TILE_N + wn * 64 + tq * 2;

#pragma unroll
  for (int i = 0; i < 4; i++) {
#pragma unroll
    for (int j = 0; j < 8; j++) {
      const size_t base = (size_t)(m0 + i * 16) * (size_t)Crows + n0 + j * 8;
      float2 lo, hi;
      lo.x = -sc * sqrtf(fmaxf(2.0f - 2.0f * acc[i][j][0], 1e-12f));
      lo.y = -sc * sqrtf(fmaxf(2.0f - 2.0f * acc[i][j][1], 1e-12f));
      hi.x = -sc * sqrtf(fmaxf(2.0f - 2.0f * acc[i][j][2], 1e-12f));
      hi.y = -sc * sqrtf(fmaxf(2.0f - 2.0f * acc[i][j][3], 1e-12f));
      *reinterpret_cast<float2*>(out + base) = lo;
      *reinterpret_cast<float2*>(out + base + 8ull * Crows) = hi;
    }
  }
}

// ------------------------------ launch -----------------------------------
extern "C" void kernel_launch(void* const* d_in, const int* in_sizes, int n_in,
                              void* d_out, int out_size) {
  const float* feats = (const float*)d_in[0];
  const float* prot  = (const float*)d_in[1];
  const float* dsc   = (const float*)d_in[2];
  float* out = (float*)d_out;

  const int N = in_sizes[0] / DDIM;   // 16384
  const int C = in_sizes[1] / DDIM;   // 8192

  void *fnp = nullptr, *pnp = nullptr;
  cudaGetSymbolAddress(&fnp, g_fn);
  cudaGetSymbolAddress(&pnp, g_pn);

  norm_pack_kernel<<<N, 256>>>(feats, (char*)fnp, TILE_M);
  norm_pack_kernel<<<C, 256>>>(prot, (char*)pnp, TILE_N);

  cudaFuncSetAttribute(gemm_dist_kernel,
                       cudaFuncAttributeMaxDynamicSharedMemorySize, SMEM_BYTES);
  const int grid = (N / TILE_M) * (C / TILE_N);   // 4096
  gemm_dist_kernel<<<grid, 256, SMEM_BYTES>>>((const char*)fnp, (const char*)pnp,
                                              dsc, out, C);
}

// round 12
// speedup vs baseline: 1.1304x; 1.1304x over previous
#include <cuda_runtime.h>
#include <cuda_fp16.h>
#include <stdint.h>

#define DDIM   2048
#define TILE_M 128
#define TILE_N 256
#define TILE_K 32
#define NKS    (DDIM / TILE_K)      // 64 k-stages per tile
#define STAGES 8
#define NMAX   16384
#define CMAX   8192

#define A_BLK  (TILE_M * TILE_K * 2)   // 8192 bytes per (m-tile, k-stage)
#define B_BLK  (TILE_N * TILE_K * 2)   // 16384 bytes
#define SLOT   (A_BLK + B_BLK)         // 24576
#define SMEM_BYTES (1024 + STAGES * SLOT)   // 197632

// Packed, pre-swizzled fp16 operands (allocation-free scratch)
__device__ __align__(1024) char g_fn[(size_t)NMAX * DDIM * 2];   // 64 MB
__device__ __align__(1024) char g_pn[(size_t)CMAX * DDIM * 2];   // 32 MB

// ------------------------------ PTX helpers -----------------------------
__device__ __forceinline__ uint32_t smem_u32(const void* p) {
  uint32_t a;
  asm("{ .reg .u64 t; cvta.to.shared.u64 t, %1; cvt.u32.u64 %0, t; }" : "=r"(a) : "l"(p));
  return a;
}

#define MBAR_INIT(a, c) asm volatile("mbarrier.init.shared.b64 [%0], %1;" :: "r"(a), "r"(c) : "memory")
#define MBAR_ARRIVE(a)  asm volatile("mbarrier.arrive.shared.b64 _, [%0];" :: "r"(a) : "memory")
#define MBAR_EXPECT_TX(a, n) \
  asm volatile("mbarrier.arrive.expect_tx.shared.b64 _, [%0], %1;" :: "r"(a), "r"(n) : "memory")

#define MBAR_WAIT(a, par) do {                                                              \
  uint32_t _m = (a); uint32_t _p = (par); uint32_t _ok;                                     \
  asm volatile("{\n\t.reg .pred p;\n\t"                                                     \
    "mbarrier.try_wait.parity.acquire.cta.shared::cta.b64 p, [%1], %2;\n\t"                 \
    "selp.b32 %0, 1, 0, p;\n\t}" : "=r"(_ok) : "r"(_m), "r"(_p) : "memory");                \
  if (!_ok) {                                                                               \
    asm volatile("{\n\t.reg .pred P1;\n\t"                                                  \
      "WL_%=:\n\t"                                                                          \
      "mbarrier.try_wait.parity.acquire.cta.shared::cta.b64 P1, [%0], %1, 0x989680;\n\t"    \
      "@P1 bra.uni WD_%=;\n\t"                                                              \
      "bra.uni WL_%=;\n\t"                                                                  \
      "WD_%=:\n\t}" :: "r"(_m), "r"(_p) : "memory");                                        \
  }                                                                                         \
} while (0)

// non-tensor bulk copy gmem -> smem with transaction-count completion (sm_90, non-a)
__device__ __forceinline__ void bulk_g2s(uint32_t dst, const void* src, uint32_t bytes,
                                         uint32_t mbar) {
  asm volatile(
    "cp.async.bulk.shared::cluster.global.mbarrier::complete_tx::bytes [%0], [%1], %2, [%3];"
    :: "r"(dst), "l"(src), "r"(bytes), "r"(mbar) : "memory");
}

__device__ __forceinline__ void ldmx4(uint32_t* r, uint32_t addr) {
  asm volatile("ldmatrix.sync.aligned.m8n8.x4.shared.b16 {%0,%1,%2,%3}, [%4];"
               : "=r"(r[0]), "=r"(r[1]), "=r"(r[2]), "=r"(r[3]) : "r"(addr));
}

// fp16 inputs, fp32 accumulator (same rate as bf16, 8x better input precision here)
__device__ __forceinline__ void mma16816(float* d, const uint32_t* a, uint32_t b0, uint32_t b1) {
  asm volatile(
    "mma.sync.aligned.m16n8k16.row.col.f32.f16.f16.f32 "
    "{%0,%1,%2,%3}, {%4,%5,%6,%7}, {%8,%9}, {%0,%1,%2,%3};"
    : "+f"(d[0]), "+f"(d[1]), "+f"(d[2]), "+f"(d[3])
    : "r"(a[0]), "r"(a[1]), "r"(a[2]), "r"(a[3]), "r"(b0), "r"(b1));
}

__device__ __forceinline__ uint32_t h2_as_u32(__half2 v) {
  return *reinterpret_cast<uint32_t*>(&v);
}

// --------------------------- normalize + pack (both operands, one launch) ----
__device__ __forceinline__ void pack4(char* rowbase, int t2, float x, float y, float z,
                                      float w, float sc, size_t bstride, uint32_t s) {
  const int kt = t2 >> 3;
  const uint32_t cp = ((uint32_t)t2 & 7) >> 1;
  const uint32_t byo = ((uint32_t)t2 & 1) * 8;
  uint2 v;
  v.x = h2_as_u32(__float22half2_rn(make_float2(x * sc, y * sc)));
  v.y = h2_as_u32(__float22half2_rn(make_float2(z * sc, w * sc)));
  *reinterpret_cast<uint2*>(rowbase + (size_t)kt * bstride + ((cp ^ s) << 4) + byo) = v;
}

__global__ void norm_pack_kernel(const float* __restrict__ srcF, char* __restrict__ dstF,
                                 const float* __restrict__ srcP, char* __restrict__ dstP,
                                 int nrowsF) {
  const bool isF = (blockIdx.x < (unsigned)nrowsF);
  const int row = isF ? blockIdx.x : (blockIdx.x - nrowsF);
  const float* src = isF ? srcF : srcP;
  char* dst = isF ? dstF : dstP;
  const int tile_rows = isF ? TILE_M : TILE_N;
  const int tid = threadIdx.x;

  const float4* s4 = reinterpret_cast<const float4*>(src + (size_t)row * DDIM);
  float4 v0 = s4[tid];
  float4 v1 = s4[tid + 256];
  float acc = v0.x * v0.x + v0.y * v0.y + v0.z * v0.z + v0.w * v0.w
            + v1.x * v1.x + v1.y * v1.y + v1.z * v1.z + v1.w * v1.w;
#pragma unroll
  for (int o = 16; o > 0; o >>= 1) acc += __shfl_xor_sync(0xFFFFFFFFu, acc, o);
  __shared__ float red[8];
  if ((tid & 31) == 0) red[tid >> 5] = acc;
  __syncthreads();
  float tot = 0.f;
#pragma unroll
  for (int i = 0; i < 8; i++) tot += red[i];
  const float sc = 1.0f / fmaxf(sqrtf(tot), 1e-12f);

  const int mt = row / tile_rows;
  const int rm = row % tile_rows;
  const size_t bstride = (size_t)tile_rows * 64;
  char* rowbase = dst + (size_t)mt * 64 * bstride + (size_t)rm * 64;
  const uint32_t s = ((uint32_t)rm >> 1) & 3;
  pack4(rowbase, tid, v0.x, v0.y, v0.z, v0.w, sc, bstride, s);
  pack4(rowbase, tid + 256, v1.x, v1.y, v1.z, v1.w, sc, bstride, s);
}

// --------------------------- persistent GEMM + distance -----------------
// R6's exact inner stage body (front-batched 16 LDSM + 128 MMA, STAGES=8,
// producer distance 7), wrapped in a persistent tile loop. The global stage
// counter runs across tile boundaries (64 % 8 == 0 keeps ring parity exact),
// so next-tile loads stream in while this tile's epilogue runs.
__global__ __launch_bounds__(256, 1)
void gemm_dist_kernel(const char* __restrict__ Apk, const char* __restrict__ Bpk,
                      const float* __restrict__ dscale,
                      float* __restrict__ out, int Crows, int total_tiles) {
  extern __shared__ __align__(1024) char smem[];
  const uint32_t sb = smem_u32(smem);
  const int tid = threadIdx.x;
  const int wid = tid >> 5;
  const int lane = tid & 31;
  const int nt = Crows / TILE_N;                 // 32
  const int grid = gridDim.x;

  const int ntiles_local = (total_tiles - blockIdx.x + grid - 1) / grid;
  const int TL = ntiles_local * NKS;

  if (tid == 0) {
#pragma unroll
    for (int s = 0; s < STAGES; s++) {
      MBAR_INIT(sb + s * 8, 1);
      MBAR_INIT(sb + 128 + s * 8, 8);
    }
  }
  __syncthreads();

  // produce global stage t: tile tl = t/64 (local), k-stage st = t%64
  auto produce = [&](int t) {
    const int tl = t >> 6;
    const int st = t & 63;
    const int idx = blockIdx.x + tl * grid;
    const int sg = idx / (4 * nt);
    const int rr = idx % (4 * nt);
    const int mt = sg * 4 + (rr & 3);
    const int ntl = rr >> 2;
    const int ts = t & (STAGES - 1);
    MBAR_WAIT(sb + 128 + ts * 8, ((t / STAGES) - 1) & 1);       // slot free
    const uint32_t full = sb + ts * 8;
    const uint32_t pslot = sb + 1024 + ts * SLOT;
    MBAR_EXPECT_TX(full, SLOT);
    bulk_g2s(pslot, Apk + (size_t)mt * NKS * A_BLK + (size_t)st * A_BLK, A_BLK, full);
    bulk_g2s(pslot + A_BLK, Bpk + (size_t)ntl * NKS * B_BLK + (size_t)st * B_BLK, B_BLK, full);
  };

  if (tid == 0) {
#pragma unroll
    for (int t = 0; t < STAGES - 1; t++) if (t < TL) produce(t);
  }

  // per-lane ldmatrix addressing constants
  const int wm = wid & 1;
  const int wn = wid >> 1;
  const uint32_t sA = (((uint32_t)lane & 15) >> 1) & 3;
  const uint32_t sB = (((uint32_t)lane & 7) >> 1) & 3;
  const uint32_t aRowOff = (uint32_t)(wm * 64 + (lane & 15)) * 64;
  const uint32_t aChunkHalf = (uint32_t)(lane >> 4);
  const uint32_t bRowOff = (uint32_t)(wn * 64 + (lane >> 4) * 8 + (lane & 7)) * 64;
  const uint32_t bChunkHalf = ((uint32_t)lane >> 3) & 1;

  const float sc = fabsf(dscale[0]);
  const int g = lane >> 2;
  const int tq = lane & 3;

  for (int lt = 0; lt < ntiles_local; lt++) {
    const int idx = blockIdx.x + lt * grid;
    const int sg = idx / (4 * nt);
    const int rr = idx % (4 * nt);
    const int m_tile = sg * 4 + (rr & 3);
    const int n_tile = rr >> 2;

    float acc[4][8][4];
#pragma unroll
    for (int i = 0; i < 4; i++)
#pragma unroll
      for (int j = 0; j < 8; j++)
#pragma unroll
        for (int c = 0; c < 4; c++) acc[i][j][c] = 0.f;

    for (int i = 0; i < NKS; i++) {
      const int s = lt * NKS + i;                 // global stage
      const int t = s + STAGES - 1;
      if (tid == 0 && t < TL) produce(t);

      const int is = s & (STAGES - 1);
      MBAR_WAIT(sb + is * 8, (s / STAGES) & 1);                 // data ready
      const uint32_t slot = sb + 1024 + (uint32_t)is * SLOT;

      // front-batch ALL 16 LDSM of this stage, then 128 independent MMAs
      uint32_t a[2][4][4], b[2][4][4];
#pragma unroll
      for (int ks = 0; ks < 2; ks++) {
        const uint32_t ca = (((uint32_t)ks * 2 + aChunkHalf) ^ sA) << 4;
        const uint32_t cb = (((uint32_t)ks * 2 + bChunkHalf) ^ sB) << 4;
#pragma unroll
        for (int ii = 0; ii < 4; ii++) ldmx4(a[ks][ii], slot + aRowOff + ii * 1024 + ca);
#pragma unroll
        for (int jp = 0; jp < 4; jp++) ldmx4(b[ks][jp], slot + A_BLK + bRowOff + jp * 1024 + cb);
      }
#pragma unroll
      for (int ks = 0; ks < 2; ks++)
#pragma unroll
        for (int ii = 0; ii < 4; ii++)
#pragma unroll
          for (int j = 0; j < 8; j++)
            mma16816(acc[ii][j], a[ks][ii],
                     b[ks][j >> 1][(j & 1) * 2], b[ks][j >> 1][(j & 1) * 2 + 1]);

      if (lane == 0) MBAR_ARRIVE(sb + 128 + is * 8);            // stage consumed
    }

    // fused distance epilogue — next tile's loads already in flight
    const int m0 = m_tile * TILE_M + wm * 64 + g;
    const int n0 = n_tile * TILE_N + wn * 64 + tq * 2;
#pragma unroll
    for (int i = 0; i < 4; i++) {
#pragma unroll
      for (int j = 0; j < 8; j++) {
        const size_t base = (size_t)(m0 + i * 16) * (size_t)Crows + n0 + j * 8;
        float2 lo, hi;
        lo.x = -sc * sqrtf(fmaxf(2.0f - 2.0f * acc[i][j][0], 1e-12f));
        lo.y = -sc * sqrtf(fmaxf(2.0f - 2.0f * acc[i][j][1], 1e-12f));
        hi.x = -sc * sqrtf(fmaxf(2.0f - 2.0f * acc[i][j][2], 1e-12f));
        hi.y = -sc * sqrtf(fmaxf(2.0f - 2.0f * acc[i][j][3], 1e-12f));
        *reinterpret_cast<float2*>(out + base) = lo;
        *reinterpret_cast<float2*>(out + base + 8ull * Crows) = hi;
      }
    }
  }
}

// ------------------------------ launch -----------------------------------
extern "C" void kernel_launch(void* const* d_in, const int* in_sizes, int n_in,
                              void* d_out, int out_size) {
  const float* feats = (const float*)d_in[0];
  const float* prot  = (const float*)d_in[1];
  const float* dsc   = (const float*)d_in[2];
  float* out = (float*)d_out;

  const int N = in_sizes[0] / DDIM;   // 16384
  const int C = in_sizes[1] / DDIM;   // 8192

  void *fnp = nullptr, *pnp = nullptr;
  cudaGetSymbolAddress(&fnp, g_fn);
  cudaGetSymbolAddress(&pnp, g_pn);

  norm_pack_kernel<<<N + C, 256>>>(feats, (char*)fnp, prot, (char*)pnp, N);

  int nsm = 148;
  {
    int dev = 0;
    cudaDeviceProp prop;
    if (cudaGetDevice(&dev) == cudaSuccess &&
        cudaGetDeviceProperties(&prop, dev) == cudaSuccess)
      nsm = prop.multiProcessorCount;   // 152 on GB300
  }

  cudaFuncSetAttribute(gemm_dist_kernel,
                       cudaFuncAttributeMaxDynamicSharedMemorySize, SMEM_BYTES);
  const int total_tiles = (N / TILE_M) * (C / TILE_N);   // 4096
  gemm_dist_kernel<<<nsm, 256, SMEM_BYTES>>>((const char*)fnp, (const char*)pnp,
                                             dsc, out, C, total_tiles);
}

// round 13
// speedup vs baseline: 1.1938x; 1.0560x over previous
#include <cuda_runtime.h>
#include <cuda_fp16.h>
#include <stdint.h>

#define DDIM   2048
#define TILE_M 128
#define TILE_N 256
#define TILE_K 32
#define NKS    (DDIM / TILE_K)      // 64 k-stages
#define STAGES 8
#define NMAX   16384
#define CMAX   8192
#define NTHREADS 512                // 16 warps: 4 per SMSP for latency hiding

#define A_BLK  (TILE_M * TILE_K * 2)   // 8192 bytes per (m-tile, k-stage)
#define B_BLK  (TILE_N * TILE_K * 2)   // 16384 bytes
#define SLOT   (A_BLK + B_BLK)         // 24576
#define SMEM_BYTES (1024 + STAGES * SLOT)   // 197632

// Packed, pre-swizzled fp16 operands (allocation-free scratch)
__device__ __align__(1024) char g_fn[(size_t)NMAX * DDIM * 2];   // 64 MB
__device__ __align__(1024) char g_pn[(size_t)CMAX * DDIM * 2];   // 32 MB

// ------------------------------ PTX helpers -----------------------------
__device__ __forceinline__ uint32_t smem_u32(const void* p) {
  uint32_t a;
  asm("{ .reg .u64 t; cvta.to.shared.u64 t, %1; cvt.u32.u64 %0, t; }" : "=r"(a) : "l"(p));
  return a;
}

#define MBAR_INIT(a, c) asm volatile("mbarrier.init.shared.b64 [%0], %1;" :: "r"(a), "r"(c) : "memory")
#define MBAR_ARRIVE(a)  asm volatile("mbarrier.arrive.shared.b64 _, [%0];" :: "r"(a) : "memory")
#define MBAR_EXPECT_TX(a, n) \
  asm volatile("mbarrier.arrive.expect_tx.shared.b64 _, [%0], %1;" :: "r"(a), "r"(n) : "memory")

#define MBAR_WAIT(a, par) do {                                                              \
  uint32_t _m = (a); uint32_t _p = (par); uint32_t _ok;                                     \
  asm volatile("{\n\t.reg .pred p;\n\t"                                                     \
    "mbarrier.try_wait.parity.acquire.cta.shared::cta.b64 p, [%1], %2;\n\t"                 \
    "selp.b32 %0, 1, 0, p;\n\t}" : "=r"(_ok) : "r"(_m), "r"(_p) : "memory");                \
  if (!_ok) {                                                                               \
    asm volatile("{\n\t.reg .pred P1;\n\t"                                                  \
      "WL_%=:\n\t"                                                                          \
      "mbarrier.try_wait.parity.acquire.cta.shared::cta.b64 P1, [%0], %1, 0x989680;\n\t"    \
      "@P1 bra.uni WD_%=;\n\t"                                                              \
      "bra.uni WL_%=;\n\t"                                                                  \
      "WD_%=:\n\t}" :: "r"(_m), "r"(_p) : "memory");                                        \
  }                                                                                         \
} while (0)

// non-tensor bulk copy gmem -> smem with transaction-count completion (sm_90, non-a)
__device__ __forceinline__ void bulk_g2s(uint32_t dst, const void* src, uint32_t bytes,
                                         uint32_t mbar) {
  asm volatile(
    "cp.async.bulk.shared::cluster.global.mbarrier::complete_tx::bytes [%0], [%1], %2, [%3];"
    :: "r"(dst), "l"(src), "r"(bytes), "r"(mbar) : "memory");
}

__device__ __forceinline__ void ldmx4(uint32_t* r, uint32_t addr) {
  asm volatile("ldmatrix.sync.aligned.m8n8.x4.shared.b16 {%0,%1,%2,%3}, [%4];"
               : "=r"(r[0]), "=r"(r[1]), "=r"(r[2]), "=r"(r[3]) : "r"(addr));
}

// fp16 inputs, fp32 accumulator
__device__ __forceinline__ void mma16816(float* d, const uint32_t* a, uint32_t b0, uint32_t b1) {
  asm volatile(
    "mma.sync.aligned.m16n8k16.row.col.f32.f16.f16.f32 "
    "{%0,%1,%2,%3}, {%4,%5,%6,%7}, {%8,%9}, {%0,%1,%2,%3};"
    : "+f"(d[0]), "+f"(d[1]), "+f"(d[2]), "+f"(d[3])
    : "r"(a[0]), "r"(a[1]), "r"(a[2]), "r"(a[3]), "r"(b0), "r"(b1));
}

__device__ __forceinline__ uint32_t h2_as_u32(__half2 v) {
  return *reinterpret_cast<uint32_t*>(&v);
}

// --------------------------- normalize + pack (both operands, one launch) ----
__device__ __forceinline__ void pack4(char* rowbase, int t2, float x, float y, float z,
                                      float w, float sc, size_t bstride, uint32_t s) {
  const int kt = t2 >> 3;
  const uint32_t cp = ((uint32_t)t2 & 7) >> 1;
  const uint32_t byo = ((uint32_t)t2 & 1) * 8;
  uint2 v;
  v.x = h2_as_u32(__float22half2_rn(make_float2(x * sc, y * sc)));
  v.y = h2_as_u32(__float22half2_rn(make_float2(z * sc, w * sc)));
  *reinterpret_cast<uint2*>(rowbase + (size_t)kt * bstride + ((cp ^ s) << 4) + byo) = v;
}

__global__ void norm_pack_kernel(const float* __restrict__ srcF, char* __restrict__ dstF,
                                 const float* __restrict__ srcP, char* __restrict__ dstP,
                                 int nrowsF) {
  const bool isF = (blockIdx.x < (unsigned)nrowsF);
  const int row = isF ? blockIdx.x : (blockIdx.x - nrowsF);
  const float* src = isF ? srcF : srcP;
  char* dst = isF ? dstF : dstP;
  const int tile_rows = isF ? TILE_M : TILE_N;
  const int tid = threadIdx.x;

  const float4* s4 = reinterpret_cast<const float4*>(src + (size_t)row * DDIM);
  float4 v0 = s4[tid];
  float4 v1 = s4[tid + 256];
  float acc = v0.x * v0.x + v0.y * v0.y + v0.z * v0.z + v0.w * v0.w
            + v1.x * v1.x + v1.y * v1.y + v1.z * v1.z + v1.w * v1.w;
#pragma unroll
  for (int o = 16; o > 0; o >>= 1) acc += __shfl_xor_sync(0xFFFFFFFFu, acc, o);
  __shared__ float red[8];
  if ((tid & 31) == 0) red[tid >> 5] = acc;
  __syncthreads();
  float tot = 0.f;
#pragma unroll
  for (int i = 0; i < 8; i++) tot += red[i];
  const float sc = 1.0f / fmaxf(sqrtf(tot), 1e-12f);

  const int mt = row / tile_rows;
  const int rm = row % tile_rows;
  const size_t bstride = (size_t)tile_rows * 64;
  char* rowbase = dst + (size_t)mt * 64 * bstride + (size_t)rm * 64;
  const uint32_t s = ((uint32_t)rm >> 1) & 3;
  pack4(rowbase, tid, v0.x, v0.y, v0.z, v0.w, sc, bstride, s);
  pack4(rowbase, tid + 256, v1.x, v1.y, v1.z, v1.w, sc, bstride, s);
}

// --------------------------- GEMM + distance ----------------------------
// CTA tile 128x256, 16 warps in 4(M)x4(N), warp tile 32x64, mma m16n8k16.
// 4 warps per SMSP: independent MMA streams cover each other's mbarrier
// waits and LDSM latency (R12 ncu: tensor pipe 34% idle at 2 warps/SMSP).
__global__ __launch_bounds__(NTHREADS, 1)
void gemm_dist_kernel(const char* __restrict__ Apk, const char* __restrict__ Bpk,
                      const float* __restrict__ dscale,
                      float* __restrict__ out, int Crows) {
  extern __shared__ __align__(1024) char smem[];
  const uint32_t sb = smem_u32(smem);
  const int tid = threadIdx.x;
  const int wid = tid >> 5;
  const int lane = tid & 31;

  // supertile mapping: groups of 4 m-tiles x all n-tiles keep B L2-resident
  const int nt = Crows / TILE_N;                 // 32
  const int per_sg = 4 * nt;                     // 128
  const int sg = blockIdx.x / per_sg;
  const int r = blockIdx.x % per_sg;
  const int m_tile = sg * 4 + (r & 3);
  const int n_tile = r >> 2;

  const char* Abase = Apk + (size_t)m_tile * NKS * A_BLK;
  const char* Bbase = Bpk + (size_t)n_tile * NKS * B_BLK;

  // barriers: full[s] @ sb + s*8 ; empty[s] @ sb + 128 + s*8
  if (tid == 0) {
#pragma unroll
    for (int s = 0; s < STAGES; s++) {
      MBAR_INIT(sb + s * 8, 1);
      MBAR_INIT(sb + 128 + s * 8, 16);           // 16 consumer warps
    }
  }
  __syncthreads();

  if (tid == 0) {
#pragma unroll
    for (int t = 0; t < STAGES - 1; t++) {
      const uint32_t full = sb + t * 8;
      const uint32_t slot = sb + 1024 + t * SLOT;
      MBAR_EXPECT_TX(full, SLOT);
      bulk_g2s(slot, Abase + (size_t)t * A_BLK, A_BLK, full);
      bulk_g2s(slot + A_BLK, Bbase + (size_t)t * B_BLK, B_BLK, full);
    }
  }

  // per-lane ldmatrix addressing: warp (wm, wn) owns rows [wm*32,+32) x cols [wn*64,+64)
  const int wm = wid & 3;
  const int wn = wid >> 2;
  const uint32_t sA = (((uint32_t)lane & 15) >> 1) & 3;
  const uint32_t sB = (((uint32_t)lane & 7) >> 1) & 3;
  const uint32_t aRowOff = (uint32_t)(wm * 32 + (lane & 15)) * 64;
  const uint32_t aChunkHalf = (uint32_t)(lane >> 4);
  const uint32_t bRowOff = (uint32_t)(wn * 64 + (lane >> 4) * 8 + (lane & 7)) * 64;
  const uint32_t bChunkHalf = ((uint32_t)lane >> 3) & 1;

  float acc[2][8][4];
#pragma unroll
  for (int i = 0; i < 2; i++)
#pragma unroll
    for (int j = 0; j < 8; j++)
#pragma unroll
      for (int c = 0; c < 4; c++) acc[i][j][c] = 0.f;

  for (int i = 0; i < NKS; i++) {
    const int t = i + STAGES - 1;
    if (t < NKS && tid == 0) {
      const int ts = t & (STAGES - 1);
      MBAR_WAIT(sb + 128 + ts * 8, ((t / STAGES) - 1) & 1);     // slot free
      const uint32_t full = sb + ts * 8;
      const uint32_t slot = sb + 1024 + ts * SLOT;
      MBAR_EXPECT_TX(full, SLOT);
      bulk_g2s(slot, Abase + (size_t)t * A_BLK, A_BLK, full);
      bulk_g2s(slot + A_BLK, Bbase + (size_t)t * B_BLK, B_BLK, full);
    }

    const int is = i & (STAGES - 1);
    MBAR_WAIT(sb + is * 8, (i / STAGES) & 1);                   // data ready
    const uint32_t slot = sb + 1024 + (uint32_t)is * SLOT;

    // front-batch all 12 LDSM of this stage, then 32 independent MMAs
    uint32_t a[2][2][4], b[2][4][4];
#pragma unroll
    for (int ks = 0; ks < 2; ks++) {
      const uint32_t ca = (((uint32_t)ks * 2 + aChunkHalf) ^ sA) << 4;
      const uint32_t cb = (((uint32_t)ks * 2 + bChunkHalf) ^ sB) << 4;
#pragma unroll
      for (int ii = 0; ii < 2; ii++) ldmx4(a[ks][ii], slot + aRowOff + ii * 1024 + ca);
#pragma unroll
      for (int jp = 0; jp < 4; jp++) ldmx4(b[ks][jp], slot + A_BLK + bRowOff + jp * 1024 + cb);
    }
#pragma unroll
    for (int ks = 0; ks < 2; ks++)
#pragma unroll
      for (int ii = 0; ii < 2; ii++)
#pragma unroll
        for (int j = 0; j < 8; j++)
          mma16816(acc[ii][j], a[ks][ii],
                   b[ks][j >> 1][(j & 1) * 2], b[ks][j >> 1][(j & 1) * 2 + 1]);

    if (lane == 0) MBAR_ARRIVE(sb + 128 + is * 8);              // slot consumed
  }

  // fused distance epilogue: each warp stores its 32x64 block
  const float sc = fabsf(dscale[0]);
  const int g = lane >> 2;
  const int tq = lane & 3;
  const int m0 = m_tile * TILE_M + wm * 32 + g;
  const int n0 = n_tile * TILE_N + wn * 64 + tq * 2;

#pragma unroll
  for (int i = 0; i < 2; i++) {
#pragma unroll
    for (int j = 0; j < 8; j++) {
      const size_t base = (size_t)(m0 + i * 16) * (size_t)Crows + n0 + j * 8;
      float2 lo, hi;
      lo.x = -sc * sqrtf(fmaxf(2.0f - 2.0f * acc[i][j][0], 1e-12f));
      lo.y = -sc * sqrtf(fmaxf(2.0f - 2.0f * acc[i][j][1], 1e-12f));
      hi.x = -sc * sqrtf(fmaxf(2.0f - 2.0f * acc[i][j][2], 1e-12f));
      hi.y = -sc * sqrtf(fmaxf(2.0f - 2.0f * acc[i][j][3], 1e-12f));
      *reinterpret_cast<float2*>(out + base) = lo;
      *reinterpret_cast<float2*>(out + base + 8ull * Crows) = hi;
    }
  }
}

// ------------------------------ launch -----------------------------------
extern "C" void kernel_launch(void* const* d_in, const int* in_sizes, int n_in,
                              void* d_out, int out_size) {
  const float* feats = (const float*)d_in[0];
  const float* prot  = (const float*)d_in[1];
  const float* dsc   = (const float*)d_in[2];
  float* out = (float*)d_out;

  const int N = in_sizes[0] / DDIM;   // 16384
  const int C = in_sizes[1] / DDIM;   // 8192

  void *fnp = nullptr, *pnp = nullptr;
  cudaGetSymbolAddress(&fnp, g_fn);
  cudaGetSymbolAddress(&pnp, g_pn);

  norm_pack_kernel<<<N + C, 256>>>(feats, (char*)fnp, prot, (char*)pnp, N);

  cudaFuncSetAttribute(gemm_dist_kernel,
                       cudaFuncAttributeMaxDynamicSharedMemorySize, SMEM_BYTES);
  const int grid = (N / TILE_M) * (C / TILE_N);   // 4096
  gemm_dist_kernel<<<grid, NTHREADS, SMEM_BYTES>>>((const char*)fnp, (const char*)pnp,
                                                   dsc, out, C);
}

// round 14
// speedup vs baseline: 1.3671x; 1.1452x over previous
#include <cuda_runtime.h>
#include <cuda_fp16.h>
#include <stdint.h>

#define DDIM   2048
#define TILE_M 128
#define TILE_N 256
#define NST    32                   // outer stages, 64 k-elements each
#define STAGES 4
#define NMAX   16384
#define CMAX   8192

#define A_SUB  (TILE_M * 32 * 2)    // 8192 B: one 32-elem packed sub-block of A
#define B_SUB  (TILE_N * 32 * 2)    // 16384 B
#define A_STG  (2 * A_SUB)          // 16384 B per stage
#define B_STG  (2 * B_SUB)          // 32768 B per stage
#define SLOT   (A_STG + B_STG)      // 49152
#define SMEM_BYTES (1024 + STAGES * SLOT)   // 197632

// Packed, pre-swizzled fp16 operands (allocation-free scratch)
__device__ __align__(1024) char g_fn[(size_t)NMAX * DDIM * 2];   // 64 MB
__device__ __align__(1024) char g_pn[(size_t)CMAX * DDIM * 2];   // 32 MB

// ------------------------------ PTX helpers -----------------------------
__device__ __forceinline__ uint32_t smem_u32(const void* p) {
  uint32_t a;
  asm("{ .reg .u64 t; cvta.to.shared.u64 t, %1; cvt.u32.u64 %0, t; }" : "=r"(a) : "l"(p));
  return a;
}

#define MBAR_INIT(a, c) asm volatile("mbarrier.init.shared.b64 [%0], %1;" :: "r"(a), "r"(c) : "memory")
#define MBAR_ARRIVE(a)  asm volatile("mbarrier.arrive.shared.b64 _, [%0];" :: "r"(a) : "memory")
#define MBAR_EXPECT_TX(a, n) \
  asm volatile("mbarrier.arrive.expect_tx.shared.b64 _, [%0], %1;" :: "r"(a), "r"(n) : "memory")

#define MBAR_WAIT(a, par) do {                                                              \
  uint32_t _m = (a); uint32_t _p = (par); uint32_t _ok;                                     \
  asm volatile("{\n\t.reg .pred p;\n\t"                                                     \
    "mbarrier.try_wait.parity.acquire.cta.shared::cta.b64 p, [%1], %2;\n\t"                 \
    "selp.b32 %0, 1, 0, p;\n\t}" : "=r"(_ok) : "r"(_m), "r"(_p) : "memory");                \
  if (!_ok) {                                                                               \
    asm volatile("{\n\t.reg .pred P1;\n\t"                                                  \
      "WL_%=:\n\t"                                                                          \
      "mbarrier.try_wait.parity.acquire.cta.shared::cta.b64 P1, [%0], %1, 0x989680;\n\t"    \
      "@P1 bra.uni WD_%=;\n\t"                                                              \
      "bra.uni WL_%=;\n\t"                                                                  \
      "WD_%=:\n\t}" :: "r"(_m), "r"(_p) : "memory");                                        \
  }                                                                                         \
} while (0)

// non-tensor bulk copy gmem -> smem with transaction-count completion (sm_90, non-a)
__device__ __forceinline__ void bulk_g2s(uint32_t dst, const void* src, uint32_t bytes,
                                         uint32_t mbar) {
  asm volatile(
    "cp.async.bulk.shared::cluster.global.mbarrier::complete_tx::bytes [%0], [%1], %2, [%3];"
    :: "r"(dst), "l"(src), "r"(bytes), "r"(mbar) : "memory");
}

__device__ __forceinline__ void ldmx4(uint32_t* r, uint32_t addr) {
  asm volatile("ldmatrix.sync.aligned.m8n8.x4.shared.b16 {%0,%1,%2,%3}, [%4];"
               : "=r"(r[0]), "=r"(r[1]), "=r"(r[2]), "=r"(r[3]) : "r"(addr));
}

// fp16 inputs, fp32 accumulator
__device__ __forceinline__ void mma16816(float* d, const uint32_t* a, uint32_t b0, uint32_t b1) {
  asm volatile(
    "mma.sync.aligned.m16n8k16.row.col.f32.f16.f16.f32 "
    "{%0,%1,%2,%3}, {%4,%5,%6,%7}, {%8,%9}, {%0,%1,%2,%3};"
    : "+f"(d[0]), "+f"(d[1]), "+f"(d[2]), "+f"(d[3])
    : "r"(a[0]), "r"(a[1]), "r"(a[2]), "r"(a[3]), "r"(b0), "r"(b1));
}

__device__ __forceinline__ uint32_t h2_as_u32(__half2 v) {
  return *reinterpret_cast<uint32_t*>(&v);
}

// --------------------------- normalize + pack (both operands, one launch) ----
// Packed layout per (row-tile mt, 32-elem k-slice kt): contiguous tile_rows*64B
// block; row rm holds its slice as 4 16B chunks, chunk c at c ^ ((rm>>1)&3).
__device__ __forceinline__ void pack4(char* rowbase, int t2, float x, float y, float z,
                                      float w, float sc, size_t bstride, uint32_t s) {
  const int kt = t2 >> 3;
  const uint32_t cp = ((uint32_t)t2 & 7) >> 1;
  const uint32_t byo = ((uint32_t)t2 & 1) * 8;
  uint2 v;
  v.x = h2_as_u32(__float22half2_rn(make_float2(x * sc, y * sc)));
  v.y = h2_as_u32(__float22half2_rn(make_float2(z * sc, w * sc)));
  *reinterpret_cast<uint2*>(rowbase + (size_t)kt * bstride + ((cp ^ s) << 4) + byo) = v;
}

__global__ void norm_pack_kernel(const float* __restrict__ srcF, char* __restrict__ dstF,
                                 const float* __restrict__ srcP, char* __restrict__ dstP,
                                 int nrowsF) {
  const bool isF = (blockIdx.x < (unsigned)nrowsF);
  const int row = isF ? blockIdx.x : (blockIdx.x - nrowsF);
  const float* src = isF ? srcF : srcP;
  char* dst = isF ? dstF : dstP;
  const int tile_rows = isF ? TILE_M : TILE_N;
  const int tid = threadIdx.x;

  const float4* s4 = reinterpret_cast<const float4*>(src + (size_t)row * DDIM);
  float4 v0 = s4[tid];
  float4 v1 = s4[tid + 256];
  float acc = v0.x * v0.x + v0.y * v0.y + v0.z * v0.z + v0.w * v0.w
            + v1.x * v1.x + v1.y * v1.y + v1.z * v1.z + v1.w * v1.w;
#pragma unroll
  for (int o = 16; o > 0; o >>= 1) acc += __shfl_xor_sync(0xFFFFFFFFu, acc, o);
  __shared__ float red[8];
  if ((tid & 31) == 0) red[tid >> 5] = acc;
  __syncthreads();
  float tot = 0.f;
#pragma unroll
  for (int i = 0; i < 8; i++) tot += red[i];
  const float sc = 1.0f / fmaxf(sqrtf(tot), 1e-12f);

  const int mt = row / tile_rows;
  const int rm = row % tile_rows;
  const size_t bstride = (size_t)tile_rows * 64;
  char* rowbase = dst + (size_t)mt * 64 * bstride + (size_t)rm * 64;
  const uint32_t s = ((uint32_t)rm >> 1) & 3;
  pack4(rowbase, tid, v0.x, v0.y, v0.z, v0.w, sc, bstride, s);
  pack4(rowbase, tid + 256, v1.x, v1.y, v1.z, v1.w, sc, bstride, s);
}

// --------------------------- GEMM + distance ----------------------------
// CTA tile 128x256, 8 warps 2(M)x4(N), warp tile 64x64, mma m16n8k16 fp16.
// R6's stage body, but stages carry 64 k-elements (two 32-elem halves),
// halving wait + producer frequency per MMA-cycle. STAGES=4 x 48KB slots.
__global__ __launch_bounds__(256, 1)
void gemm_dist_kernel(const char* __restrict__ Apk, const char* __restrict__ Bpk,
                      const float* __restrict__ dscale,
                      float* __restrict__ out, int Crows) {
  extern __shared__ __align__(1024) char smem[];
  const uint32_t sb = smem_u32(smem);
  const int tid = threadIdx.x;
  const int wid = tid >> 5;
  const int lane = tid & 31;

  // supertile mapping: groups of 4 m-tiles x all n-tiles keep B L2-resident
  const int nt = Crows / TILE_N;                 // 32
  const int per_sg = 4 * nt;                     // 128
  const int sg = blockIdx.x / per_sg;
  const int r = blockIdx.x % per_sg;
  const int m_tile = sg * 4 + (r & 3);
  const int n_tile = r >> 2;

  const char* Abase = Apk + (size_t)m_tile * NST * A_STG;
  const char* Bbase = Bpk + (size_t)n_tile * NST * B_STG;

  // barriers: full[s] @ sb + s*8 ; empty[s] @ sb + 128 + s*8
  if (tid == 0) {
#pragma unroll
    for (int s = 0; s < STAGES; s++) {
      MBAR_INIT(sb + s * 8, 1);
      MBAR_INIT(sb + 128 + s * 8, 8);
    }
  }
  __syncthreads();

  auto produce = [&](int t, bool waitEmpty) {
    const int ts = t & (STAGES - 1);
    if (waitEmpty) MBAR_WAIT(sb + 128 + ts * 8, ((t / STAGES) - 1) & 1);
    const uint32_t full = sb + ts * 8;
    const uint32_t slot = sb + 1024 + (uint32_t)ts * SLOT;
    MBAR_EXPECT_TX(full, SLOT);
    bulk_g2s(slot, Abase + (size_t)t * A_STG, A_STG, full);
    bulk_g2s(slot + A_STG, Bbase + (size_t)t * B_STG, B_STG, full);
  };

  if (tid == 0) {
#pragma unroll
    for (int t = 0; t < STAGES - 1; t++) produce(t, false);
  }

  // per-lane ldmatrix addressing constants
  const int wm = wid & 1;
  const int wn = wid >> 1;
  const uint32_t sA = (((uint32_t)lane & 15) >> 1) & 3;
  const uint32_t sB = (((uint32_t)lane & 7) >> 1) & 3;
  const uint32_t aRowOff = (uint32_t)(wm * 64 + (lane & 15)) * 64;
  const uint32_t aChunkHalf = (uint32_t)(lane >> 4);
  const uint32_t bRowOff = (uint32_t)(wn * 64 + (lane >> 4) * 8 + (lane & 7)) * 64;
  const uint32_t bChunkHalf = ((uint32_t)lane >> 3) & 1;

  float acc[4][8][4];
#pragma unroll
  for (int i = 0; i < 4; i++)
#pragma unroll
    for (int j = 0; j < 8; j++)
#pragma unroll
      for (int c = 0; c < 4; c++) acc[i][j][c] = 0.f;

  for (int i = 0; i < NST; i++) {
    const int t = i + STAGES - 1;
    if (t < NST && tid == 0) produce(t, true);

    const int is = i & (STAGES - 1);
    MBAR_WAIT(sb + is * 8, (i / STAGES) & 1);                   // data ready
    const uint32_t slot = sb + 1024 + (uint32_t)is * SLOT;

    // two 32-elem halves; each: front-batch 16 LDSM, then 128 independent MMAs
#pragma unroll
    for (int h = 0; h < 2; h++) {
      const uint32_t abase = slot + (uint32_t)h * A_SUB;
      const uint32_t bbase = slot + A_STG + (uint32_t)h * B_SUB;
      uint32_t a[2][4][4], b[2][4][4];
#pragma unroll
      for (int ks = 0; ks < 2; ks++) {
        const uint32_t ca = (((uint32_t)ks * 2 + aChunkHalf) ^ sA) << 4;
        const uint32_t cb = (((uint32_t)ks * 2 + bChunkHalf) ^ sB) << 4;
#pragma unroll
        for (int ii = 0; ii < 4; ii++) ldmx4(a[ks][ii], abase + aRowOff + ii * 1024 + ca);
#pragma unroll
        for (int jp = 0; jp < 4; jp++) ldmx4(b[ks][jp], bbase + bRowOff + jp * 1024 + cb);
      }
#pragma unroll
      for (int ks = 0; ks < 2; ks++)
#pragma unroll
        for (int ii = 0; ii < 4; ii++)
#pragma unroll
          for (int j = 0; j < 8; j++)
            mma16816(acc[ii][j], a[ks][ii],
                     b[ks][j >> 1][(j & 1) * 2], b[ks][j >> 1][(j & 1) * 2 + 1]);
    }

    if (lane == 0) MBAR_ARRIVE(sb + 128 + is * 8);              // stage consumed
  }

  // fused distance epilogue
  const float sc = fabsf(dscale[0]);
  const int g = lane >> 2;
  const int tq = lane & 3;
  const int m0 = m_tile * TILE_M + wm * 64 + g;
  const int n0 = n_tile * TILE_N + wn * 64 + tq * 2;

#pragma unroll
  for (int i = 0; i < 4; i++) {
#pragma unroll
    for (int j = 0; j < 8; j++) {
      const size_t base = (size_t)(m0 + i * 16) * (size_t)Crows + n0 + j * 8;
      float2 lo, hi;
      lo.x = -sc * sqrtf(fmaxf(2.0f - 2.0f * acc[i][j][0], 1e-12f));
      lo.y = -sc * sqrtf(fmaxf(2.0f - 2.0f * acc[i][j][1], 1e-12f));
      hi.x = -sc * sqrtf(fmaxf(2.0f - 2.0f * acc[i][j][2], 1e-12f));
      hi.y = -sc * sqrtf(fmaxf(2.0f - 2.0f * acc[i][j][3], 1e-12f));
      *reinterpret_cast<float2*>(out + base) = lo;
      *reinterpret_cast<float2*>(out + base + 8ull * Crows) = hi;
    }
  }
}

// ------------------------------ launch -----------------------------------
extern "C" void kernel_launch(void* const* d_in, const int* in_sizes, int n_in,
                              void* d_out, int out_size) {
  const float* feats = (const float*)d_in[0];
  const float* prot  = (const float*)d_in[1];
  const float* dsc   = (const float*)d_in[2];
  float* out = (float*)d_out;

  const int N = in_sizes[0] / DDIM;   // 16384
  const int C = in_sizes[1] / DDIM;   // 8192

  void *fnp = nullptr, *pnp = nullptr;
  cudaGetSymbolAddress(&fnp, g_fn);
  cudaGetSymbolAddress(&pnp, g_pn);

  norm_pack_kernel<<<N + C, 256>>>(feats, (char*)fnp, prot, (char*)pnp, N);

  cudaFuncSetAttribute(gemm_dist_kernel,
                       cudaFuncAttributeMaxDynamicSharedMemorySize, SMEM_BYTES);
  const int grid = (N / TILE_M) * (C / TILE_N);   // 4096
  gemm_dist_kernel<<<grid, 256, SMEM_BYTES>>>((const char*)fnp, (const char*)pnp,
                                              dsc, out, C);
}

// round 15
// speedup vs baseline: 1.4258x; 1.0429x over previous
#include <cuda_runtime.h>
#include <cuda_fp16.h>
#include <stdint.h>

#define DDIM   2048
#define TILE_M 128
#define TILE_N 256
#define NST    32                   // outer stages, 64 k-elements each
#define STAGES 4
#define NMAX   16384
#define CMAX   8192

#define A_SUB  (TILE_M * 32 * 2)    // 8192 B: one 32-elem packed sub-block of A
#define B_SUB  (TILE_N * 32 * 2)    // 16384 B
#define A_STG  (2 * A_SUB)          // 16384 B per stage
#define B_STG  (2 * B_SUB)          // 32768 B per stage
#define SLOT   (A_STG + B_STG)      // 49152
#define SMEM_BYTES (1024 + STAGES * SLOT)   // 197632

// Packed, pre-swizzled fp16 operands (allocation-free scratch)
__device__ __align__(1024) char g_fn[(size_t)NMAX * DDIM * 2];   // 64 MB
__device__ __align__(1024) char g_pn[(size_t)CMAX * DDIM * 2];   // 32 MB

// ------------------------------ PTX helpers -----------------------------
__device__ __forceinline__ uint32_t smem_u32(const void* p) {
  uint32_t a;
  asm("{ .reg .u64 t; cvta.to.shared.u64 t, %1; cvt.u32.u64 %0, t; }" : "=r"(a) : "l"(p));
  return a;
}

#define MBAR_INIT(a, c) asm volatile("mbarrier.init.shared.b64 [%0], %1;" :: "r"(a), "r"(c) : "memory")
#define MBAR_ARRIVE(a)  asm volatile("mbarrier.arrive.shared.b64 _, [%0];" :: "r"(a) : "memory")
#define MBAR_EXPECT_TX(a, n) \
  asm volatile("mbarrier.arrive.expect_tx.shared.b64 _, [%0], %1;" :: "r"(a), "r"(n) : "memory")

#define MBAR_WAIT(a, par) do {                                                              \
  uint32_t _m = (a); uint32_t _p = (par); uint32_t _ok;                                     \
  asm volatile("{\n\t.reg .pred p;\n\t"                                                     \
    "mbarrier.try_wait.parity.acquire.cta.shared::cta.b64 p, [%1], %2;\n\t"                 \
    "selp.b32 %0, 1, 0, p;\n\t}" : "=r"(_ok) : "r"(_m), "r"(_p) : "memory");                \
  if (!_ok) {                                                                               \
    asm volatile("{\n\t.reg .pred P1;\n\t"                                                  \
      "WL_%=:\n\t"                                                                          \
      "mbarrier.try_wait.parity.acquire.cta.shared::cta.b64 P1, [%0], %1, 0x989680;\n\t"    \
      "@P1 bra.uni WD_%=;\n\t"                                                              \
      "bra.uni WL_%=;\n\t"                                                                  \
      "WD_%=:\n\t}" :: "r"(_m), "r"(_p) : "memory");                                        \
  }                                                                                         \
} while (0)

// non-tensor bulk copy gmem -> smem with transaction-count completion (sm_90, non-a)
__device__ __forceinline__ void bulk_g2s(uint32_t dst, const void* src, uint32_t bytes,
                                         uint32_t mbar) {
  asm volatile(
    "cp.async.bulk.shared::cluster.global.mbarrier::complete_tx::bytes [%0], [%1], %2, [%3];"
    :: "r"(dst), "l"(src), "r"(bytes), "r"(mbar) : "memory");
}

__device__ __forceinline__ void ldmx4(uint32_t* r, uint32_t addr) {
  asm volatile("ldmatrix.sync.aligned.m8n8.x4.shared.b16 {%0,%1,%2,%3}, [%4];"
               : "=r"(r[0]), "=r"(r[1]), "=r"(r[2]), "=r"(r[3]) : "r"(addr));
}

// fp16 inputs, fp32 accumulator
__device__ __forceinline__ void mma16816(float* d, const uint32_t* a, uint32_t b0, uint32_t b1) {
  asm volatile(
    "mma.sync.aligned.m16n8k16.row.col.f32.f16.f16.f32 "
    "{%0,%1,%2,%3}, {%4,%5,%6,%7}, {%8,%9}, {%0,%1,%2,%3};"
    : "+f"(d[0]), "+f"(d[1]), "+f"(d[2]), "+f"(d[3])
    : "r"(a[0]), "r"(a[1]), "r"(a[2]), "r"(a[3]), "r"(b0), "r"(b1));
}

__device__ __forceinline__ uint32_t h2_as_u32(__half2 v) {
  return *reinterpret_cast<uint32_t*>(&v);
}

__device__ __forceinline__ float sqrt_approx(float x) {
  float r;
  asm("sqrt.approx.f32 %0, %1;" : "=f"(r) : "f"(x));
  return r;
}

// --------------------------- normalize + pack (both operands, one launch) ----
// Packed layout per (row-tile mt, 32-elem k-slice kt): contiguous tile_rows*64B
// block; row rm holds its slice as 4 16B chunks, chunk c at c ^ ((rm>>1)&3).
__device__ __forceinline__ void pack4(char* rowbase, int t2, float x, float y, float z,
                                      float w, float sc, size_t bstride, uint32_t s) {
  const int kt = t2 >> 3;
  const uint32_t cp = ((uint32_t)t2 & 7) >> 1;
  const uint32_t byo = ((uint32_t)t2 & 1) * 8;
  uint2 v;
  v.x = h2_as_u32(__float22half2_rn(make_float2(x * sc, y * sc)));
  v.y = h2_as_u32(__float22half2_rn(make_float2(z * sc, w * sc)));
  *reinterpret_cast<uint2*>(rowbase + (size_t)kt * bstride + ((cp ^ s) << 4) + byo) = v;
}

__global__ void norm_pack_kernel(const float* __restrict__ srcF, char* __restrict__ dstF,
                                 const float* __restrict__ srcP, char* __restrict__ dstP,
                                 int nrowsF) {
  const bool isF = (blockIdx.x < (unsigned)nrowsF);
  const int row = isF ? blockIdx.x : (blockIdx.x - nrowsF);
  const float* src = isF ? srcF : srcP;
  char* dst = isF ? dstF : dstP;
  const int tile_rows = isF ? TILE_M : TILE_N;
  const int tid = threadIdx.x;

  const float4* s4 = reinterpret_cast<const float4*>(src + (size_t)row * DDIM);
  float4 v0 = s4[tid];
  float4 v1 = s4[tid + 256];
  float acc = v0.x * v0.x + v0.y * v0.y + v0.z * v0.z + v0.w * v0.w
            + v1.x * v1.x + v1.y * v1.y + v1.z * v1.z + v1.w * v1.w;
#pragma unroll
  for (int o = 16; o > 0; o >>= 1) acc += __shfl_xor_sync(0xFFFFFFFFu, acc, o);
  __shared__ float red[8];
  if ((tid & 31) == 0) red[tid >> 5] = acc;
  __syncthreads();
  float tot = 0.f;
#pragma unroll
  for (int i = 0; i < 8; i++) tot += red[i];
  const float sc = 1.0f / fmaxf(sqrtf(tot), 1e-12f);

  const int mt = row / tile_rows;
  const int rm = row % tile_rows;
  const size_t bstride = (size_t)tile_rows * 64;
  char* rowbase = dst + (size_t)mt * 64 * bstride + (size_t)rm * 64;
  const uint32_t s = ((uint32_t)rm >> 1) & 3;
  pack4(rowbase, tid, v0.x, v0.y, v0.z, v0.w, sc, bstride, s);
  pack4(rowbase, tid + 256, v1.x, v1.y, v1.z, v1.w, sc, bstride, s);
}

// --------------------------- GEMM + distance ----------------------------
// CTA tile 128x256, 8 warps 2(M)x4(N), warp tile 64x64, mma m16n8k16 fp16.
// 64-elem k-stages (STAGES=4 x 48KB). Producer duty round-robin: stage t is
// produced by warp (t & 7), so no single warp carries the per-stage
// empty-wait + bulk-issue lag.
__global__ __launch_bounds__(256, 1)
void gemm_dist_kernel(const char* __restrict__ Apk, const char* __restrict__ Bpk,
                      const float* __restrict__ dscale,
                      float* __restrict__ out, int Crows) {
  extern __shared__ __align__(1024) char smem[];
  const uint32_t sb = smem_u32(smem);
  const int tid = threadIdx.x;
  const int wid = tid >> 5;
  const int lane = tid & 31;

  // supertile mapping: groups of 4 m-tiles x all n-tiles keep B L2-resident
  const int nt = Crows / TILE_N;                 // 32
  const int per_sg = 4 * nt;                     // 128
  const int sg = blockIdx.x / per_sg;
  const int r = blockIdx.x % per_sg;
  const int m_tile = sg * 4 + (r & 3);
  const int n_tile = r >> 2;

  const char* Abase = Apk + (size_t)m_tile * NST * A_STG;
  const char* Bbase = Bpk + (size_t)n_tile * NST * B_STG;

  // barriers: full[s] @ sb + s*8 ; empty[s] @ sb + 128 + s*8
  if (tid == 0) {
#pragma unroll
    for (int s = 0; s < STAGES; s++) {
      MBAR_INIT(sb + s * 8, 1);
      MBAR_INIT(sb + 128 + s * 8, 8);
    }
  }
  __syncthreads();

  auto produce = [&](int t, bool waitEmpty) {
    const int ts = t & (STAGES - 1);
    if (waitEmpty) MBAR_WAIT(sb + 128 + ts * 8, ((t / STAGES) - 1) & 1);
    const uint32_t full = sb + ts * 8;
    const uint32_t slot = sb + 1024 + (uint32_t)ts * SLOT;
    MBAR_EXPECT_TX(full, SLOT);
    bulk_g2s(slot, Abase + (size_t)t * A_STG, A_STG, full);
    bulk_g2s(slot + A_STG, Bbase + (size_t)t * B_STG, B_STG, full);
  };

  if (tid == 0) {
#pragma unroll
    for (int t = 0; t < STAGES - 1; t++) produce(t, false);
  }

  // per-lane ldmatrix addressing constants
  const int wm = wid & 1;
  const int wn = wid >> 1;
  const uint32_t sA = (((uint32_t)lane & 15) >> 1) & 3;
  const uint32_t sB = (((uint32_t)lane & 7) >> 1) & 3;
  const uint32_t aRowOff = (uint32_t)(wm * 64 + (lane & 15)) * 64;
  const uint32_t aChunkHalf = (uint32_t)(lane >> 4);
  const uint32_t bRowOff = (uint32_t)(wn * 64 + (lane >> 4) * 8 + (lane & 7)) * 64;
  const uint32_t bChunkHalf = ((uint32_t)lane >> 3) & 1;

  float acc[4][8][4];
#pragma unroll
  for (int i = 0; i < 4; i++)
#pragma unroll
    for (int j = 0; j < 8; j++)
#pragma unroll
      for (int c = 0; c < 4; c++) acc[i][j][c] = 0.f;

  for (int i = 0; i < NST; i++) {
    const int t = i + STAGES - 1;
    // round-robin producer: warp (t & 7), lane 0. At iteration i this warp
    // has already consumed stage i-1 = t-4, so its empty-wait cannot
    // self-deadlock; the barrier covers the other 7 warps.
    if (t < NST && wid == (t & 7) && lane == 0) produce(t, true);

    const int is = i & (STAGES - 1);
    MBAR_WAIT(sb + is * 8, (i / STAGES) & 1);                   // data ready
    const uint32_t slot = sb + 1024 + (uint32_t)is * SLOT;

    // two 32-elem halves; each: front-batch 16 LDSM, then 128 independent MMAs
#pragma unroll
    for (int h = 0; h < 2; h++) {
      const uint32_t abase = slot + (uint32_t)h * A_SUB;
      const uint32_t bbase = slot + A_STG + (uint32_t)h * B_SUB;
      uint32_t a[2][4][4], b[2][4][4];
#pragma unroll
      for (int ks = 0; ks < 2; ks++) {
        const uint32_t ca = (((uint32_t)ks * 2 + aChunkHalf) ^ sA) << 4;
        const uint32_t cb = (((uint32_t)ks * 2 + bChunkHalf) ^ sB) << 4;
#pragma unroll
        for (int ii = 0; ii < 4; ii++) ldmx4(a[ks][ii], abase + aRowOff + ii * 1024 + ca);
#pragma unroll
        for (int jp = 0; jp < 4; jp++) ldmx4(b[ks][jp], bbase + bRowOff + jp * 1024 + cb);
      }
#pragma unroll
      for (int ks = 0; ks < 2; ks++)
#pragma unroll
        for (int ii = 0; ii < 4; ii++)
#pragma unroll
          for (int j = 0; j < 8; j++)
            mma16816(acc[ii][j], a[ks][ii],
                     b[ks][j >> 1][(j & 1) * 2], b[ks][j >> 1][(j & 1) * 2 + 1]);
    }

    if (lane == 0) MBAR_ARRIVE(sb + 128 + is * 8);              // stage consumed
  }

  // fused distance epilogue (sqrt.approx: 1-2 ulp, threshold is 1e-3)
  const float sc = fabsf(dscale[0]);
  const int g = lane >> 2;
  const int tq = lane & 3;
  const int m0 = m_tile * TILE_M + wm * 64 + g;
  const int n0 = n_tile * TILE_N + wn * 64 + tq * 2;

#pragma unroll
  for (int i = 0; i < 4; i++) {
#pragma unroll
    for (int j = 0; j < 8; j++) {
      const size_t base = (size_t)(m0 + i * 16) * (size_t)Crows + n0 + j * 8;
      float2 lo, hi;
      lo.x = -sc * sqrt_approx(fmaxf(2.0f - 2.0f * acc[i][j][0], 1e-12f));
      lo.y = -sc * sqrt_approx(fmaxf(2.0f - 2.0f * acc[i][j][1], 1e-12f));
      hi.x = -sc * sqrt_approx(fmaxf(2.0f - 2.0f * acc[i][j][2], 1e-12f));
      hi.y = -sc * sqrt_approx(fmaxf(2.0f - 2.0f * acc[i][j][3], 1e-12f));
      *reinterpret_cast<float2*>(out + base) = lo;
      *reinterpret_cast<float2*>(out + base + 8ull * Crows) = hi;
    }
  }
}

// ------------------------------ launch -----------------------------------
extern "C" void kernel_launch(void* const* d_in, const int* in_sizes, int n_in,
                              void* d_out, int out_size) {
  const float* feats = (const float*)d_in[0];
  const float* prot  = (const float*)d_in[1];
  const float* dsc   = (const float*)d_in[2];
  float* out = (float*)d_out;

  const int N = in_sizes[0] / DDIM;   // 16384
  const int C = in_sizes[1] / DDIM;   // 8192

  void *fnp = nullptr, *pnp = nullptr;
  cudaGetSymbolAddress(&fnp, g_fn);
  cudaGetSymbolAddress(&pnp, g_pn);

  norm_pack_kernel<<<N + C, 256>>>(feats, (char*)fnp, prot, (char*)pnp, N);

  cudaFuncSetAttribute(gemm_dist_kernel,
                       cudaFuncAttributeMaxDynamicSharedMemorySize, SMEM_BYTES);
  const int grid = (N / TILE_M) * (C / TILE_N);   // 4096
  gemm_dist_kernel<<<grid, 256, SMEM_BYTES>>>((const char*)fnp, (const char*)pnp,
                                              dsc, out, C);
}

// round 16
// speedup vs baseline: 1.4550x; 1.0205x over previous
#include <cuda_runtime.h>
#include <cuda_fp16.h>
#include <stdint.h>

#define DDIM   2048
#define TILE_M 128
#define TILE_N 256
#define NST    16                   // outer stages, 128 k-elements each
#define STAGES 2
#define NMAX   16384
#define CMAX   8192

#define A_SUB  (TILE_M * 32 * 2)    // 8192 B: one 32-elem packed sub-block of A
#define B_SUB  (TILE_N * 32 * 2)    // 16384 B
#define NSUB   4                    // sub-blocks per stage (128 k-elements)
#define A_STG  (NSUB * A_SUB)       // 32768 B per stage
#define B_STG  (NSUB * B_SUB)       // 65536 B per stage
#define SLOT   (A_STG + B_STG)      // 98304
#define SMEM_BYTES (1024 + STAGES * SLOT)   // 197632

// Packed, pre-swizzled fp16 operands (allocation-free scratch)
__device__ __align__(1024) char g_fn[(size_t)NMAX * DDIM * 2];   // 64 MB
__device__ __align__(1024) char g_pn[(size_t)CMAX * DDIM * 2];   // 32 MB

// ------------------------------ PTX helpers -----------------------------
__device__ __forceinline__ uint32_t smem_u32(const void* p) {
  uint32_t a;
  asm("{ .reg .u64 t; cvta.to.shared.u64 t, %1; cvt.u32.u64 %0, t; }" : "=r"(a) : "l"(p));
  return a;
}

#define MBAR_INIT(a, c) asm volatile("mbarrier.init.shared.b64 [%0], %1;" :: "r"(a), "r"(c) : "memory")
#define MBAR_ARRIVE(a)  asm volatile("mbarrier.arrive.shared.b64 _, [%0];" :: "r"(a) : "memory")
#define MBAR_EXPECT_TX(a, n) \
  asm volatile("mbarrier.arrive.expect_tx.shared.b64 _, [%0], %1;" :: "r"(a), "r"(n) : "memory")

#define MBAR_WAIT(a, par) do {                                                              \
  uint32_t _m = (a); uint32_t _p = (par); uint32_t _ok;                                     \
  asm volatile("{\n\t.reg .pred p;\n\t"                                                     \
    "mbarrier.try_wait.parity.acquire.cta.shared::cta.b64 p, [%1], %2;\n\t"                 \
    "selp.b32 %0, 1, 0, p;\n\t}" : "=r"(_ok) : "r"(_m), "r"(_p) : "memory");                \
  if (!_ok) {                                                                               \
    asm volatile("{\n\t.reg .pred P1;\n\t"                                                  \
      "WL_%=:\n\t"                                                                          \
      "mbarrier.try_wait.parity.acquire.cta.shared::cta.b64 P1, [%0], %1, 0x989680;\n\t"    \
      "@P1 bra.uni WD_%=;\n\t"                                                              \
      "bra.uni WL_%=;\n\t"                                                                  \
      "WD_%=:\n\t}" :: "r"(_m), "r"(_p) : "memory");                                        \
  }                                                                                         \
} while (0)

// non-tensor bulk copy gmem -> smem with transaction-count completion (sm_90, non-a)
__device__ __forceinline__ void bulk_g2s(uint32_t dst, const void* src, uint32_t bytes,
                                         uint32_t mbar) {
  asm volatile(
    "cp.async.bulk.shared::cluster.global.mbarrier::complete_tx::bytes [%0], [%1], %2, [%3];"
    :: "r"(dst), "l"(src), "r"(bytes), "r"(mbar) : "memory");
}

__device__ __forceinline__ void ldmx4(uint32_t* r, uint32_t addr) {
  asm volatile("ldmatrix.sync.aligned.m8n8.x4.shared.b16 {%0,%1,%2,%3}, [%4];"
               : "=r"(r[0]), "=r"(r[1]), "=r"(r[2]), "=r"(r[3]) : "r"(addr));
}

// fp16 inputs, fp32 accumulator
__device__ __forceinline__ void mma16816(float* d, const uint32_t* a, uint32_t b0, uint32_t b1) {
  asm volatile(
    "mma.sync.aligned.m16n8k16.row.col.f32.f16.f16.f32 "
    "{%0,%1,%2,%3}, {%4,%5,%6,%7}, {%8,%9}, {%0,%1,%2,%3};"
    : "+f"(d[0]), "+f"(d[1]), "+f"(d[2]), "+f"(d[3])
    : "r"(a[0]), "r"(a[1]), "r"(a[2]), "r"(a[3]), "r"(b0), "r"(b1));
}

__device__ __forceinline__ uint32_t h2_as_u32(__half2 v) {
  return *reinterpret_cast<uint32_t*>(&v);
}

__device__ __forceinline__ float sqrt_approx(float x) {
  float r;
  asm("sqrt.approx.f32 %0, %1;" : "=f"(r) : "f"(x));
  return r;
}

// --------------------------- normalize + pack (both operands, one launch) ----
// Packed layout per (row-tile mt, 32-elem k-slice kt): contiguous tile_rows*64B
// block; row rm holds its slice as 4 16B chunks, chunk c at c ^ ((rm>>1)&3).
__device__ __forceinline__ void pack4(char* rowbase, int t2, float x, float y, float z,
                                      float w, float sc, size_t bstride, uint32_t s) {
  const int kt = t2 >> 3;
  const uint32_t cp = ((uint32_t)t2 & 7) >> 1;
  const uint32_t byo = ((uint32_t)t2 & 1) * 8;
  uint2 v;
  v.x = h2_as_u32(__float22half2_rn(make_float2(x * sc, y * sc)));
  v.y = h2_as_u32(__float22half2_rn(make_float2(z * sc, w * sc)));
  *reinterpret_cast<uint2*>(rowbase + (size_t)kt * bstride + ((cp ^ s) << 4) + byo) = v;
}

__global__ void norm_pack_kernel(const float* __restrict__ srcF, char* __restrict__ dstF,
                                 const float* __restrict__ srcP, char* __restrict__ dstP,
                                 int nrowsF) {
  const bool isF = (blockIdx.x < (unsigned)nrowsF);
  const int row = isF ? blockIdx.x : (blockIdx.x - nrowsF);
  const float* src = isF ? srcF : srcP;
  char* dst = isF ? dstF : dstP;
  const int tile_rows = isF ? TILE_M : TILE_N;
  const int tid = threadIdx.x;

  const float4* s4 = reinterpret_cast<const float4*>(src + (size_t)row * DDIM);
  float4 v0 = s4[tid];
  float4 v1 = s4[tid + 256];
  float acc = v0.x * v0.x + v0.y * v0.y + v0.z * v0.z + v0.w * v0.w
            + v1.x * v1.x + v1.y * v1.y + v1.z * v1.z + v1.w * v1.w;
#pragma unroll
  for (int o = 16; o > 0; o >>= 1) acc += __shfl_xor_sync(0xFFFFFFFFu, acc, o);
  __shared__ float red[8];
  if ((tid & 31) == 0) red[tid >> 5] = acc;
  __syncthreads();
  float tot = 0.f;
#pragma unroll
  for (int i = 0; i < 8; i++) tot += red[i];
  const float sc = 1.0f / fmaxf(sqrtf(tot), 1e-12f);

  const int mt = row / tile_rows;
  const int rm = row % tile_rows;
  const size_t bstride = (size_t)tile_rows * 64;
  char* rowbase = dst + (size_t)mt * 64 * bstride + (size_t)rm * 64;
  const uint32_t s = ((uint32_t)rm >> 1) & 3;
  pack4(rowbase, tid, v0.x, v0.y, v0.z, v0.w, sc, bstride, s);
  pack4(rowbase, tid + 256, v1.x, v1.y, v1.z, v1.w, sc, bstride, s);
}

// --------------------------- GEMM + distance ----------------------------
// CTA tile 128x256, 8 warps 2(M)x4(N), warp tile 64x64, mma m16n8k16 fp16.
// 128-elem k-stages (STAGES=2 x 96KB): stage-boundary events (full-wait +
// produce) halved again vs R15. Producer duty round-robin over warps.
__global__ __launch_bounds__(256, 1)
void gemm_dist_kernel(const char* __restrict__ Apk, const char* __restrict__ Bpk,
                      const float* __restrict__ dscale,
                      float* __restrict__ out, int Crows) {
  extern __shared__ __align__(1024) char smem[];
  const uint32_t sb = smem_u32(smem);
  const int tid = threadIdx.x;
  const int wid = tid >> 5;
  const int lane = tid & 31;

  // supertile mapping: groups of 4 m-tiles x all n-tiles keep B L2-resident
  const int nt = Crows / TILE_N;                 // 32
  const int per_sg = 4 * nt;                     // 128
  const int sg = blockIdx.x / per_sg;
  const int r = blockIdx.x % per_sg;
  const int m_tile = sg * 4 + (r & 3);
  const int n_tile = r >> 2;

  const char* Abase = Apk + (size_t)m_tile * NST * A_STG;
  const char* Bbase = Bpk + (size_t)n_tile * NST * B_STG;

  // barriers: full[s] @ sb + s*8 ; empty[s] @ sb + 128 + s*8
  if (tid == 0) {
#pragma unroll
    for (int s = 0; s < STAGES; s++) {
      MBAR_INIT(sb + s * 8, 1);
      MBAR_INIT(sb + 128 + s * 8, 8);
    }
  }
  __syncthreads();

  auto produce = [&](int t, bool waitEmpty) {
    const int ts = t & (STAGES - 1);
    if (waitEmpty) MBAR_WAIT(sb + 128 + ts * 8, ((t / STAGES) - 1) & 1);
    const uint32_t full = sb + ts * 8;
    const uint32_t slot = sb + 1024 + (uint32_t)ts * SLOT;
    MBAR_EXPECT_TX(full, SLOT);
    bulk_g2s(slot, Abase + (size_t)t * A_STG, A_STG, full);
    bulk_g2s(slot + A_STG, Bbase + (size_t)t * B_STG, B_STG, full);
  };

  if (tid == 0) {
#pragma unroll
    for (int t = 0; t < STAGES - 1; t++) produce(t, false);
  }

  // per-lane ldmatrix addressing constants
  const int wm = wid & 1;
  const int wn = wid >> 1;
  const uint32_t sA = (((uint32_t)lane & 15) >> 1) & 3;
  const uint32_t sB = (((uint32_t)lane & 7) >> 1) & 3;
  const uint32_t aRowOff = (uint32_t)(wm * 64 + (lane & 15)) * 64;
  const uint32_t aChunkHalf = (uint32_t)(lane >> 4);
  const uint32_t bRowOff = (uint32_t)(wn * 64 + (lane >> 4) * 8 + (lane & 7)) * 64;
  const uint32_t bChunkHalf = ((uint32_t)lane >> 3) & 1;

  float acc[4][8][4];
#pragma unroll
  for (int i = 0; i < 4; i++)
#pragma unroll
    for (int j = 0; j < 8; j++)
#pragma unroll
      for (int c = 0; c < 4; c++) acc[i][j][c] = 0.f;

  for (int i = 0; i < NST; i++) {
    const int t = i + STAGES - 1;
    // round-robin producer: warp (t & 7), lane 0. At iteration i this warp
    // already arrived on empty[slot of stage i-1] (same slot t targets), so
    // its empty-wait covers only the other 7 warps — no self-deadlock.
    if (t < NST && wid == (t & 7) && lane == 0) produce(t, true);

    const int is = i & (STAGES - 1);
    MBAR_WAIT(sb + is * 8, (i / STAGES) & 1);                   // data ready
    const uint32_t slot = sb + 1024 + (uint32_t)is * SLOT;

    // four 32-elem sub-blocks; each: front-batch 16 LDSM + 128 independent MMAs
#pragma unroll
    for (int h = 0; h < NSUB; h++) {
      const uint32_t abase = slot + (uint32_t)h * A_SUB;
      const uint32_t bbase = slot + A_STG + (uint32_t)h * B_SUB;
      uint32_t a[2][4][4], b[2][4][4];
#pragma unroll
      for (int ks = 0; ks < 2; ks++) {
        const uint32_t ca = (((uint32_t)ks * 2 + aChunkHalf) ^ sA) << 4;
        const uint32_t cb = (((uint32_t)ks * 2 + bChunkHalf) ^ sB) << 4;
#pragma unroll
        for (int ii = 0; ii < 4; ii++) ldmx4(a[ks][ii], abase + aRowOff + ii * 1024 + ca);
#pragma unroll
        for (int jp = 0; jp < 4; jp++) ldmx4(b[ks][jp], bbase + bRowOff + jp * 1024 + cb);
      }
#pragma unroll
      for (int ks = 0; ks < 2; ks++)
#pragma unroll
        for (int ii = 0; ii < 4; ii++)
#pragma unroll
          for (int j = 0; j < 8; j++)
            mma16816(acc[ii][j], a[ks][ii],
                     b[ks][j >> 1][(j & 1) * 2], b[ks][j >> 1][(j & 1) * 2 + 1]);
    }

    if (lane == 0) MBAR_ARRIVE(sb + 128 + is * 8);              // stage consumed
  }

  // fused distance epilogue (sqrt.approx: 1-2 ulp, threshold is 1e-3)
  const float sc = fabsf(dscale[0]);
  const int g = lane >> 2;
  const int tq = lane & 3;
  const int m0 = m_tile * TILE_M + wm * 64 + g;
  const int n0 = n_tile * TILE_N + wn * 64 + tq * 2;

#pragma unroll
  for (int i = 0; i < 4; i++) {
#pragma unroll
    for (int j = 0; j < 8; j++) {
      const size_t base = (size_t)(m0 + i * 16) * (size_t)Crows + n0 + j * 8;
      float2 lo, hi;
      lo.x = -sc * sqrt_approx(fmaxf(2.0f - 2.0f * acc[i][j][0], 1e-12f));
      lo.y = -sc * sqrt_approx(fmaxf(2.0f - 2.0f * acc[i][j][1], 1e-12f));
      hi.x = -sc * sqrt_approx(fmaxf(2.0f - 2.0f * acc[i][j][2], 1e-12f));
      hi.y = -sc * sqrt_approx(fmaxf(2.0f - 2.0f * acc[i][j][3], 1e-12f));
      *reinterpret_cast<float2*>(out + base) = lo;
      *reinterpret_cast<float2*>(out + base + 8ull * Crows) = hi;
    }
  }
}

// ------------------------------ launch -----------------------------------
extern "C" void kernel_launch(void* const* d_in, const int* in_sizes, int n_in,
                              void* d_out, int out_size) {
  const float* feats = (const float*)d_in[0];
  const float* prot  = (const float*)d_in[1];
  const float* dsc   = (const float*)d_in[2];
  float* out = (float*)d_out;

  const int N = in_sizes[0] / DDIM;   // 16384
  const int C = in_sizes[1] / DDIM;   // 8192

  void *fnp = nullptr, *pnp = nullptr;
  cudaGetSymbolAddress(&fnp, g_fn);
  cudaGetSymbolAddress(&pnp, g_pn);

  norm_pack_kernel<<<N + C, 256>>>(feats, (char*)fnp, prot, (char*)pnp, N);

  cudaFuncSetAttribute(gemm_dist_kernel,
                       cudaFuncAttributeMaxDynamicSharedMemorySize, SMEM_BYTES);
  const int grid = (N / TILE_M) * (C / TILE_N);   // 4096
  gemm_dist_kernel<<<grid, 256, SMEM_BYTES>>>((const char*)fnp, (const char*)pnp,
                                              dsc, out, C);
}